// round 16
// baseline (speedup 1.0000x reference)
#include <cuda_runtime.h>
#include <math.h>
#include <stdint.h>

#define D_IN   768
#define TWO_D  1536
#define Q_N    128
#define S_N    512
#define C_N    64
#define JCHUNKS 8
#define JPER   (TWO_D / JCHUNKS)    /* 192 */
#define KSPLIT 384
#define NCB    32                   /* chunk-blocks = JCHUNKS * 4 s-tiles */

typedef unsigned long long ull;

// Scratch (device globals: allocation-free per harness rules)
__device__ float    v16_hq0[Q_N * TWO_D];
__device__ float    v16_hq1[Q_N * TWO_D];
__device__ float    v16_hs0[S_N * TWO_D];
__device__ float    v16_hs1[S_N * TWO_D];
__device__ double   v16_part2[NCB * Q_N * C_N];     // class-binned partials (2 MB)
__device__ double   v16_loss[Q_N];
__device__ unsigned v16_ticket = 0;

// fp32 -> tf32 RNA rounding (matches cuBLAS TF32 input quantization = reference)
__device__ __forceinline__ float v16_tf32(float x) {
    unsigned u;
    asm("cvt.rna.tf32.f32 %0, %1;" : "=r"(u) : "f"(x));
    return __uint_as_float(u);
}

// m16n8k8 tf32 mma (base ISA, sm_80+)
__device__ __forceinline__ void v16_mma(float d[4], const unsigned a[4], const unsigned b[2]) {
    asm volatile(
        "mma.sync.aligned.m16n8k8.row.col.f32.tf32.tf32.f32 "
        "{%0,%1,%2,%3}, {%4,%5,%6,%7}, {%8,%9}, {%0,%1,%2,%3};"
        : "+f"(d[0]), "+f"(d[1]), "+f"(d[2]), "+f"(d[3])
        : "r"(a[0]), "r"(a[1]), "r"(a[2]), "r"(a[3]), "r"(b[0]), "r"(b[1]));
}

#define V16_ADD2(d, a, b) \
    asm("add.rn.f32x2 %0, %1, %2;" : "=l"(d) : "l"(a), "l"(b))
#define V16_FMA2(acc, t, w) \
    asm("fma.rn.f32x2 %0, %1, %2, %0;" : "+l"(acc) : "l"(t), "l"(w))

// packed relu on the ALU pipe (IMAX): valid for all non-NaN floats
__device__ __forceinline__ ull v16_relu2(ull t) {
    unsigned lo, hi;
    asm("mov.b64 {%0,%1}, %2;" : "=r"(lo), "=r"(hi) : "l"(t));
    int l2 = max((int)lo, 0);
    int h2 = max((int)hi, 0);
    ull r;
    asm("mov.b64 %0, {%1,%2};" : "=l"(r) : "r"((unsigned)l2), "r"((unsigned)h2));
    return r;
}

// ---------------------------------------------------------------------------
// TF32 tensor-core GEMM, split-K x2 (VERBATIM best-measured config, 26 us).
// CTA 64m x 128n x K384; 12 double-buffered k-tiles of 32, one barrier/iter.
// 8 warps (2M x 4N), warp tile 32x32. grid = (12, 10, 2), occupancy 2.
// ---------------------------------------------------------------------------
#define V16_ST     40
#define V16_ASZ    (2 * 64 * V16_ST)
#define V16_BSZ    (2 * 128 * V16_ST)
#define V16_SMEM   ((V16_ASZ + V16_BSZ) * 4)

__global__ void __launch_bounds__(256, 2)
v16_gemm(const float* __restrict__ query,
         const float* __restrict__ support,
         const float* __restrict__ W1,
         const float* __restrict__ b1)
{
    extern __shared__ __align__(16) float smem[];
    float* As = smem;
    float* Bs = smem + V16_ASZ;

    const int tid  = threadIdx.x;
    const int lane = tid & 31;
    const int wid  = tid >> 5;
    const int warpM = wid & 1;
    const int warpN = wid >> 1;
    const int g = lane >> 2;
    const int t = lane & 3;

    const int  z    = blockIdx.z;
    const int  kOff = z * KSPLIT;
    const bool isQ  = (blockIdx.y < 2);
    const float* Arow = isQ ? (query + (size_t)blockIdx.y * 64 * D_IN)
                            : (support + (size_t)(blockIdx.y - 2) * 64 * D_IN);
    const int   wOff  = (isQ ? 0 : D_IN) + kOff;
    const int   jBase = blockIdx.x * 128;
    float* Hq = z ? v16_hq1 : v16_hq0;
    float* Hs = z ? v16_hs1 : v16_hs0;
    float* Crow = isQ ? (Hq + (size_t)blockIdx.y * 64 * TWO_D)
                      : (Hs + (size_t)(blockIdx.y - 2) * 64 * TWO_D);

    const int a_row = tid >> 2, a_ks = tid & 3;
    const int b_row0 = tid >> 2, b_ks0 = tid & 3;
    const int b_row1 = (tid + 256) >> 2, b_ks1 = tid & 3;
    const float* aSeg  = Arow + (size_t)a_row * D_IN + kOff + a_ks * 8;
    const float* bSeg0 = W1 + (size_t)(jBase + b_row0) * TWO_D + wOff + b_ks0 * 8;
    const float* bSeg1 = W1 + (size_t)(jBase + b_row1) * TWO_D + wOff + b_ks1 * 8;

    float4 pa0, pa1, pb00, pb01, pb10, pb11;
    #define V16_PREFETCH(kb) do {                                   \
        pa0  = *(const float4*)(aSeg  + (kb));                      \
        pa1  = *(const float4*)(aSeg  + (kb) + 4);                  \
        pb00 = *(const float4*)(bSeg0 + (kb));                      \
        pb01 = *(const float4*)(bSeg0 + (kb) + 4);                  \
        pb10 = *(const float4*)(bSeg1 + (kb));                      \
        pb11 = *(const float4*)(bSeg1 + (kb) + 4);                  \
    } while (0)

    #define V16_STAGE(buf) do {                                                     \
        float* ap = As + ((buf) * 64 + a_row) * V16_ST + a_ks * 8;                  \
        float2 p;                                                                   \
        p.x = v16_tf32(pa0.x); p.y = v16_tf32(pa1.x); *(float2*)(ap + 0) = p;       \
        p.x = v16_tf32(pa0.y); p.y = v16_tf32(pa1.y); *(float2*)(ap + 2) = p;       \
        p.x = v16_tf32(pa0.z); p.y = v16_tf32(pa1.z); *(float2*)(ap + 4) = p;       \
        p.x = v16_tf32(pa0.w); p.y = v16_tf32(pa1.w); *(float2*)(ap + 6) = p;       \
        float* bp = Bs + ((buf) * 128 + b_row0) * V16_ST + b_ks0 * 8;               \
        p.x = v16_tf32(pb00.x); p.y = v16_tf32(pb01.x); *(float2*)(bp + 0) = p;     \
        p.x = v16_tf32(pb00.y); p.y = v16_tf32(pb01.y); *(float2*)(bp + 2) = p;     \
        p.x = v16_tf32(pb00.z); p.y = v16_tf32(pb01.z); *(float2*)(bp + 4) = p;     \
        p.x = v16_tf32(pb00.w); p.y = v16_tf32(pb01.w); *(float2*)(bp + 6) = p;     \
        bp = Bs + ((buf) * 128 + b_row1) * V16_ST + b_ks1 * 8;                      \
        p.x = v16_tf32(pb10.x); p.y = v16_tf32(pb11.x); *(float2*)(bp + 0) = p;     \
        p.x = v16_tf32(pb10.y); p.y = v16_tf32(pb11.y); *(float2*)(bp + 2) = p;     \
        p.x = v16_tf32(pb10.z); p.y = v16_tf32(pb11.z); *(float2*)(bp + 4) = p;     \
        p.x = v16_tf32(pb10.w); p.y = v16_tf32(pb11.w); *(float2*)(bp + 6) = p;     \
    } while (0)

    float d[2][4][4] = {};

    V16_PREFETCH(0);
    V16_STAGE(0);
    V16_PREFETCH(32);

    for (int kt = 0; kt < 12; kt++) {
        const int buf = kt & 1;
        __syncthreads();
        if (kt < 11) {
            V16_STAGE(buf ^ 1);
            if (kt < 10) V16_PREFETCH((kt + 2) * 32);
        }

        const float* Ab = As + buf * 64 * V16_ST;
        const float* Bb = Bs + buf * 128 * V16_ST;
        #pragma unroll
        for (int s = 0; s < 4; s++) {
            unsigned afr[2][4];
            #pragma unroll
            for (int mf = 0; mf < 2; mf++) {
                const int r0 = warpM * 32 + mf * 16 + g;
                float2 p0 = *(const float2*)(Ab + r0 * V16_ST + s * 8 + t * 2);
                float2 p1 = *(const float2*)(Ab + (r0 + 8) * V16_ST + s * 8 + t * 2);
                afr[mf][0] = __float_as_uint(p0.x);
                afr[mf][1] = __float_as_uint(p1.x);
                afr[mf][2] = __float_as_uint(p0.y);
                afr[mf][3] = __float_as_uint(p1.y);
            }
            #pragma unroll
            for (int nf = 0; nf < 4; nf++) {
                const int n = warpN * 32 + nf * 8 + g;
                float2 q = *(const float2*)(Bb + n * V16_ST + s * 8 + t * 2);
                unsigned bfr[2] = { __float_as_uint(q.x), __float_as_uint(q.y) };
                v16_mma(d[0][nf], afr[0], bfr);
                v16_mma(d[1][nf], afr[1], bfr);
            }
        }
    }

    const bool addBias = isQ && (z == 0);
    #pragma unroll
    for (int mf = 0; mf < 2; mf++) {
        const int r0 = warpM * 32 + mf * 16 + g;
        #pragma unroll
        for (int nf = 0; nf < 4; nf++) {
            const int c0 = jBase + warpN * 32 + nf * 8 + t * 2;
            float2 bias = make_float2(0.f, 0.f);
            if (addBias) bias = *(const float2*)(b1 + c0);
            float2 v0 = make_float2(d[mf][nf][0] + bias.x, d[mf][nf][1] + bias.y);
            float2 v1 = make_float2(d[mf][nf][2] + bias.x, d[mf][nf][3] + bias.y);
            *(float2*)(Crow + (size_t)r0 * TWO_D + c0)       = v0;
            *(float2*)(Crow + (size_t)(r0 + 8) * TWO_D + c0) = v1;
        }
    }
}

// ---------------------------------------------------------------------------
// Scores + class binning, 1024 threads (8 warps/SMSP at 1 block/SM).
// Per-thread tile 2q x 2s; per-(q,s) accumulation order identical to R12/R15
// -> bit-identical part2. Same 128 binning epilogues and agg interface.
// grid = (4 s-tiles, 4 q-stripes, 8 j-chunks), 1024 threads.
// ---------------------------------------------------------------------------
#define V16S_DYN   33824   /* bytes: scr 33024 + lab 512 + seg 260 + pad */

__global__ void __launch_bounds__(1024, 1)
v16_scores(const float* __restrict__ W2, const int* __restrict__ labels)
{
    extern __shared__ __align__(16) char dyn[];
    float2* Aq2 = (float2*)(dyn);                 // [2][8][34]
    float2* Bs2 = (float2*)(dyn + 4352);          // [2][8][130]
    float2* ws2 = (float2*)(dyn + 20992);         // [2][8]
    double* scr  = (double*)(dyn);                // [32][129] (phase 2 overlay)
    int*    lab2 = (int*)(dyn + 33024);           // [128]
    int*    seg  = (int*)(dyn + 33536);           // [65]

    const int tid    = threadIdx.x;
    const int sBase  = blockIdx.x * 128;
    const int qBase  = blockIdx.y * 32;
    const int jcBase = blockIdx.z * JPER;
    const int ty = tid >> 6;      // 0..15: q rows ty*2, ty*2+1 (warp-uniform)
    const int tx = tid & 63;      // s cols tx + l*64, l=0..1

    // A staging: threads 0..255, one f32x2 each (32 q x 8 jp)
    const int aq_q  = (tid >> 3) & 31;
    const int aq_jp = tid & 7;
    const size_t hqOff = (size_t)(qBase + aq_q) * TWO_D + jcBase + aq_jp * 2;
    // B staging: all 1024, one f32x2 each (128 s x 8 jp), 64B coalesced per 8 tids
    const int bs_s  = tid >> 3;          // 0..127
    const int bs_jp = tid & 7;
    const size_t hsOff = (size_t)(sBase + bs_s) * TWO_D + jcBase + bs_jp * 2;

    float2 pa0, pa1, pb0, pb1, pw;

    #define V16S_PRE(jt) do {                                              \
        if (tid < 256) {                                                   \
            pa0 = *(const float2*)(v16_hq0 + hqOff + (jt));                \
            pa1 = *(const float2*)(v16_hq1 + hqOff + (jt));                \
        }                                                                  \
        pb0 = *(const float2*)(v16_hs0 + hsOff + (jt));                    \
        pb1 = *(const float2*)(v16_hs1 + hsOff + (jt));                    \
        if (tid < 8) pw = *(const float2*)(W2 + jcBase + (jt) + tid * 2);  \
    } while (0)

    #define V16S_STAGE(buf) do {                                                            \
        if (tid < 256)                                                                       \
            Aq2[(buf)*272 + aq_jp*34 + aq_q] = make_float2(pa0.x + pa1.x, pa0.y + pa1.y);   \
        Bs2[(buf)*1040 + bs_jp*130 + bs_s] = make_float2(pb0.x + pb1.x, pb0.y + pb1.y);     \
        if (tid < 8) ws2[(buf)*8 + tid] = pw;                                               \
    } while (0)

    ull acc2[2][2] = {};

    V16S_PRE(0);
    V16S_STAGE(0);
    V16S_PRE(16);

    for (int it = 0; it < 12; it++) {
        const int buf = it & 1;
        __syncthreads();
        if (it < 11) {
            V16S_STAGE(buf ^ 1);
            if (it < 10) V16S_PRE((it + 2) * 16);
        }

        #pragma unroll
        for (int jp = 0; jp < 8; jp++) {
            const ull w2v = *(const ull*)&ws2[buf*8 + jp];
            // one LDS128 (warp-uniform broadcast): q-pair rows ty*2, ty*2+1
            float4 apair = *(const float4*)&Aq2[buf*272 + jp*34 + ty*2];
            ull a0, a1;
            asm("mov.b64 %0, {%1,%2};" : "=l"(a0)
                : "r"(__float_as_uint(apair.x)), "r"(__float_as_uint(apair.y)));
            asm("mov.b64 %0, {%1,%2};" : "=l"(a1)
                : "r"(__float_as_uint(apair.z)), "r"(__float_as_uint(apair.w)));
            #pragma unroll
            for (int l = 0; l < 2; l++) {
                const ull bv = *(const ull*)&Bs2[buf*1040 + jp*130 + tx + l*64];
                ull t0; V16_ADD2(t0, a0, bv);
                t0 = v16_relu2(t0);
                V16_FMA2(acc2[0][l], t0, w2v);
                ull t1; V16_ADD2(t1, a1, bv);
                t1 = v16_relu2(t1);
                V16_FMA2(acc2[1][l], t1, w2v);
            }
        }
    }

    // ---- phase 2: overlay smem, write chunk scores, bin by class ----
    __syncthreads();

    #pragma unroll
    for (int i = 0; i < 2; i++)
        #pragma unroll
        for (int l = 0; l < 2; l++) {
            unsigned lo, hi;
            asm("mov.b64 {%0,%1}, %2;" : "=r"(lo), "=r"(hi) : "l"(acc2[i][l]));
            scr[(ty*2 + i) * 129 + tx + l*64] =
                (double)(__uint_as_float(lo) + __uint_as_float(hi));
        }
    if (tid < 128) lab2[tid] = labels[sBase + tid];
    __syncthreads();

    if (tid <= 64) {
        const int c = tid;
        int lo = 0, hi = 128;
        while (lo < hi) { int m = (lo + hi) >> 1; if (lab2[m] < c) lo = m + 1; else hi = m; }
        seg[tid] = lo;
    }
    __syncthreads();

    const int cb = blockIdx.z * 4 + blockIdx.x;
    double* outp = v16_part2 + ((size_t)cb * Q_N + qBase) * C_N;
    #pragma unroll
    for (int k = 0; k < 2; k++) {
        const int p  = tid + k * 1024;
        const int qq = p >> 6;
        const int cc = p & 63;
        double ssum = 0.0;
        const int s0 = seg[cc], s1 = seg[cc + 1];
        for (int s = s0; s < s1; s++) ssum += scr[qq * 129 + s];
        outp[p] = ssum;
    }
}

// ---------------------------------------------------------------------------
// Light aggregate (VERBATIM R12): per-query block sums 32 class-binned
// partials in fixed order, counts via binary search, softmax/argmax/loss,
// ticket-merged final. grid = 128 blocks, 128 threads.
// ---------------------------------------------------------------------------
__global__ void v16_agg(const int* __restrict__ labels,
                        const int* __restrict__ targets,
                        const float* __restrict__ b2,
                        float* __restrict__ out, int out_size)
{
    __shared__ int    lab[S_N];
    __shared__ double aggv[C_N];
    __shared__ double redv[C_N];
    __shared__ int    redi[C_N];
    __shared__ double rede[C_N];
    __shared__ int    isLast;
    __shared__ double lred[Q_N];

    const int q   = blockIdx.x;
    const int tid = threadIdx.x;

    for (int i = tid; i < S_N; i += 128) lab[i] = labels[i];
    __syncthreads();

    if (tid < C_N) {
        const double* P = v16_part2 + (size_t)q * C_N + tid;
        double s0 = 0.0, s1 = 0.0, s2 = 0.0, s3 = 0.0;
        #pragma unroll
        for (int cb = 0; cb < NCB; cb += 4) {
            s0 += P[(size_t)(cb + 0) * (Q_N * C_N)];
            s1 += P[(size_t)(cb + 1) * (Q_N * C_N)];
            s2 += P[(size_t)(cb + 2) * (Q_N * C_N)];
            s3 += P[(size_t)(cb + 3) * (Q_N * C_N)];
        }
        const double tot = (s0 + s1) + (s2 + s3);

        const int c = tid;
        int lo = 0, hi = S_N;
        while (lo < hi) { int m = (lo + hi) >> 1; if (lab[m] < c) lo = m + 1; else hi = m; }
        int lo2 = lo, hi2 = S_N;
        while (lo2 < hi2) { int m = (lo2 + hi2) >> 1; if (lab[m] < c + 1) lo2 = m + 1; else hi2 = m; }
        const int cnt = lo2 - lo;

        aggv[tid] = tot / (double)(cnt > 1 ? cnt : 1) + (double)b2[0];
        redv[tid] = aggv[tid];
        redi[tid] = tid;
    }
    __syncthreads();

    #pragma unroll
    for (int off = C_N / 2; off > 0; off >>= 1) {
        if (tid < off) {
            if (redv[tid + off] > redv[tid] ||
                (redv[tid + off] == redv[tid] && redi[tid + off] < redi[tid])) {
                redv[tid] = redv[tid + off];
                redi[tid] = redi[tid + off];
            }
        }
        __syncthreads();
    }
    const double mx = redv[0];
    const int    am = redi[0];

    if (tid < C_N) rede[tid] = exp(aggv[tid] - mx);
    __syncthreads();
    #pragma unroll
    for (int off = C_N / 2; off > 0; off >>= 1) {
        if (tid < off) rede[tid] += rede[tid + off];
        __syncthreads();
    }

    if (tid == 0) {
        const int tgt = targets[q];
        const double logp = aggv[tgt] - mx - log(rede[0]);
        v16_loss[q] = -logp;
        if (1 + q < out_size) out[1 + q] = (am == tgt) ? 1.0f : 0.0f;
        __threadfence();
        unsigned tk = atomicAdd(&v16_ticket, 1u);
        isLast = (tk == (unsigned)(Q_N - 1));
    }
    __syncthreads();

    if (isLast) {
        __threadfence();
        lred[tid] = v16_loss[tid];
        __syncthreads();
        #pragma unroll
        for (int off = Q_N / 2; off > 0; off >>= 1) {
            if (tid < off) lred[tid] += lred[tid + off];
            __syncthreads();
        }
        if (tid == 0) {
            if (out_size > 0) out[0] = (float)(lred[0] / (double)Q_N);
            v16_ticket = 0;
        }
    }
}

// ---------------------------------------------------------------------------
extern "C" void kernel_launch(void* const* d_in, const int* in_sizes, int n_in,
                              void* d_out, int out_size)
{
    const float* query   = (const float*)d_in[0];
    const float* support = (const float*)d_in[1];
    const float* W1      = (const float*)d_in[2];
    const float* b1      = (const float*)d_in[3];
    const float* W2      = (const float*)d_in[4];
    const float* b2      = (const float*)d_in[5];
    const int*   labels  = (const int*)  d_in[6];
    const int*   targets = (const int*)  d_in[7];
    (void)in_sizes; (void)n_in;

    float* out = (float*)d_out;

    cudaFuncSetAttribute(v16_gemm, cudaFuncAttributeMaxDynamicSharedMemorySize, V16_SMEM);

    v16_gemm  <<<dim3(12, 10, 2), 256, V16_SMEM>>>(query, support, W1, b1);
    v16_scores<<<dim3(4, 4, JCHUNKS), 1024, V16S_DYN>>>(W2, labels);
    v16_agg   <<<Q_N, 128>>>(labels, targets, b2, out, out_size);
}

// round 17
// speedup vs baseline: 1.0376x; 1.0376x over previous
#include <cuda_runtime.h>
#include <math.h>
#include <stdint.h>

#define D_IN   768
#define TWO_D  1536
#define Q_N    128
#define S_N    512
#define C_N    64
#define JCHUNKS 8
#define JPER   (TWO_D / JCHUNKS)    /* 192 */
#define KSPLIT 384
#define NCB    32                   /* chunk-blocks = JCHUNKS * 4 s-tiles */

typedef unsigned long long ull;

// Scratch (device globals: allocation-free per harness rules)
__device__ float    v17_hq0[Q_N * TWO_D];
__device__ float    v17_hq1[Q_N * TWO_D];
__device__ float    v17_hs0[S_N * TWO_D];
__device__ float    v17_hs1[S_N * TWO_D];
__device__ double   v17_part2[NCB * Q_N * C_N];     // class-binned partials (2 MB)
__device__ double   v17_loss[Q_N];
__device__ unsigned v17_ticket = 0;

// fp32 -> tf32 RNA rounding (matches cuBLAS TF32 input quantization = reference)
__device__ __forceinline__ float v17_tf32(float x) {
    unsigned u;
    asm("cvt.rna.tf32.f32 %0, %1;" : "=r"(u) : "f"(x));
    return __uint_as_float(u);
}

// m16n8k8 tf32 mma (base ISA, sm_80+)
__device__ __forceinline__ void v17_mma(float d[4], const unsigned a[4], const unsigned b[2]) {
    asm volatile(
        "mma.sync.aligned.m16n8k8.row.col.f32.tf32.tf32.f32 "
        "{%0,%1,%2,%3}, {%4,%5,%6,%7}, {%8,%9}, {%0,%1,%2,%3};"
        : "+f"(d[0]), "+f"(d[1]), "+f"(d[2]), "+f"(d[3])
        : "r"(a[0]), "r"(a[1]), "r"(a[2]), "r"(a[3]), "r"(b[0]), "r"(b[1]));
}

#define V17_ADD2(d, a, b) \
    asm("add.rn.f32x2 %0, %1, %2;" : "=l"(d) : "l"(a), "l"(b))
#define V17_FMA2(acc, t, w) \
    asm("fma.rn.f32x2 %0, %1, %2, %0;" : "+l"(acc) : "l"(t), "l"(w))

// packed relu on the ALU pipe (IMAX): valid for all non-NaN floats
__device__ __forceinline__ ull v17_relu2(ull t) {
    unsigned lo, hi;
    asm("mov.b64 {%0,%1}, %2;" : "=r"(lo), "=r"(hi) : "l"(t));
    int l2 = max((int)lo, 0);
    int h2 = max((int)hi, 0);
    ull r;
    asm("mov.b64 %0, {%1,%2};" : "=l"(r) : "r"((unsigned)l2), "r"((unsigned)h2));
    return r;
}

// ---------------------------------------------------------------------------
// TF32 tensor-core GEMM, split-K x2 (VERBATIM best-measured config, 26 us).
// CTA 64m x 128n x K384; 12 double-buffered k-tiles of 32, one barrier/iter.
// 8 warps (2M x 4N), warp tile 32x32. grid = (12, 10, 2), occupancy 2.
// ---------------------------------------------------------------------------
#define V17_ST     40
#define V17_ASZ    (2 * 64 * V17_ST)
#define V17_BSZ    (2 * 128 * V17_ST)
#define V17_SMEM   ((V17_ASZ + V17_BSZ) * 4)

__global__ void __launch_bounds__(256, 2)
v17_gemm(const float* __restrict__ query,
         const float* __restrict__ support,
         const float* __restrict__ W1,
         const float* __restrict__ b1)
{
    extern __shared__ __align__(16) float smem[];
    float* As = smem;
    float* Bs = smem + V17_ASZ;

    const int tid  = threadIdx.x;
    const int lane = tid & 31;
    const int wid  = tid >> 5;
    const int warpM = wid & 1;
    const int warpN = wid >> 1;
    const int g = lane >> 2;
    const int t = lane & 3;

    const int  z    = blockIdx.z;
    const int  kOff = z * KSPLIT;
    const bool isQ  = (blockIdx.y < 2);
    const float* Arow = isQ ? (query + (size_t)blockIdx.y * 64 * D_IN)
                            : (support + (size_t)(blockIdx.y - 2) * 64 * D_IN);
    const int   wOff  = (isQ ? 0 : D_IN) + kOff;
    const int   jBase = blockIdx.x * 128;
    float* Hq = z ? v17_hq1 : v17_hq0;
    float* Hs = z ? v17_hs1 : v17_hs0;
    float* Crow = isQ ? (Hq + (size_t)blockIdx.y * 64 * TWO_D)
                      : (Hs + (size_t)(blockIdx.y - 2) * 64 * TWO_D);

    const int a_row = tid >> 2, a_ks = tid & 3;
    const int b_row0 = tid >> 2, b_ks0 = tid & 3;
    const int b_row1 = (tid + 256) >> 2, b_ks1 = tid & 3;
    const float* aSeg  = Arow + (size_t)a_row * D_IN + kOff + a_ks * 8;
    const float* bSeg0 = W1 + (size_t)(jBase + b_row0) * TWO_D + wOff + b_ks0 * 8;
    const float* bSeg1 = W1 + (size_t)(jBase + b_row1) * TWO_D + wOff + b_ks1 * 8;

    float4 pa0, pa1, pb00, pb01, pb10, pb11;
    #define V17_PREFETCH(kb) do {                                   \
        pa0  = *(const float4*)(aSeg  + (kb));                      \
        pa1  = *(const float4*)(aSeg  + (kb) + 4);                  \
        pb00 = *(const float4*)(bSeg0 + (kb));                      \
        pb01 = *(const float4*)(bSeg0 + (kb) + 4);                  \
        pb10 = *(const float4*)(bSeg1 + (kb));                      \
        pb11 = *(const float4*)(bSeg1 + (kb) + 4);                  \
    } while (0)

    #define V17_STAGE(buf) do {                                                     \
        float* ap = As + ((buf) * 64 + a_row) * V17_ST + a_ks * 8;                  \
        float2 p;                                                                   \
        p.x = v17_tf32(pa0.x); p.y = v17_tf32(pa1.x); *(float2*)(ap + 0) = p;       \
        p.x = v17_tf32(pa0.y); p.y = v17_tf32(pa1.y); *(float2*)(ap + 2) = p;       \
        p.x = v17_tf32(pa0.z); p.y = v17_tf32(pa1.z); *(float2*)(ap + 4) = p;       \
        p.x = v17_tf32(pa0.w); p.y = v17_tf32(pa1.w); *(float2*)(ap + 6) = p;       \
        float* bp = Bs + ((buf) * 128 + b_row0) * V17_ST + b_ks0 * 8;               \
        p.x = v17_tf32(pb00.x); p.y = v17_tf32(pb01.x); *(float2*)(bp + 0) = p;     \
        p.x = v17_tf32(pb00.y); p.y = v17_tf32(pb01.y); *(float2*)(bp + 2) = p;     \
        p.x = v17_tf32(pb00.z); p.y = v17_tf32(pb01.z); *(float2*)(bp + 4) = p;     \
        p.x = v17_tf32(pb00.w); p.y = v17_tf32(pb01.w); *(float2*)(bp + 6) = p;     \
        bp = Bs + ((buf) * 128 + b_row1) * V17_ST + b_ks1 * 8;                      \
        p.x = v17_tf32(pb10.x); p.y = v17_tf32(pb11.x); *(float2*)(bp + 0) = p;     \
        p.x = v17_tf32(pb10.y); p.y = v17_tf32(pb11.y); *(float2*)(bp + 2) = p;     \
        p.x = v17_tf32(pb10.z); p.y = v17_tf32(pb11.z); *(float2*)(bp + 4) = p;     \
        p.x = v17_tf32(pb10.w); p.y = v17_tf32(pb11.w); *(float2*)(bp + 6) = p;     \
    } while (0)

    float d[2][4][4] = {};

    V17_PREFETCH(0);
    V17_STAGE(0);
    V17_PREFETCH(32);

    for (int kt = 0; kt < 12; kt++) {
        const int buf = kt & 1;
        __syncthreads();
        if (kt < 11) {
            V17_STAGE(buf ^ 1);
            if (kt < 10) V17_PREFETCH((kt + 2) * 32);
        }

        const float* Ab = As + buf * 64 * V17_ST;
        const float* Bb = Bs + buf * 128 * V17_ST;
        #pragma unroll
        for (int s = 0; s < 4; s++) {
            unsigned afr[2][4];
            #pragma unroll
            for (int mf = 0; mf < 2; mf++) {
                const int r0 = warpM * 32 + mf * 16 + g;
                float2 p0 = *(const float2*)(Ab + r0 * V17_ST + s * 8 + t * 2);
                float2 p1 = *(const float2*)(Ab + (r0 + 8) * V17_ST + s * 8 + t * 2);
                afr[mf][0] = __float_as_uint(p0.x);
                afr[mf][1] = __float_as_uint(p1.x);
                afr[mf][2] = __float_as_uint(p0.y);
                afr[mf][3] = __float_as_uint(p1.y);
            }
            #pragma unroll
            for (int nf = 0; nf < 4; nf++) {
                const int n = warpN * 32 + nf * 8 + g;
                float2 q = *(const float2*)(Bb + n * V17_ST + s * 8 + t * 2);
                unsigned bfr[2] = { __float_as_uint(q.x), __float_as_uint(q.y) };
                v17_mma(d[0][nf], afr[0], bfr);
                v17_mma(d[1][nf], afr[1], bfr);
            }
        }
    }

    const bool addBias = isQ && (z == 0);
    #pragma unroll
    for (int mf = 0; mf < 2; mf++) {
        const int r0 = warpM * 32 + mf * 16 + g;
        #pragma unroll
        for (int nf = 0; nf < 4; nf++) {
            const int c0 = jBase + warpN * 32 + nf * 8 + t * 2;
            float2 bias = make_float2(0.f, 0.f);
            if (addBias) bias = *(const float2*)(b1 + c0);
            float2 v0 = make_float2(d[mf][nf][0] + bias.x, d[mf][nf][1] + bias.y);
            float2 v1 = make_float2(d[mf][nf][2] + bias.x, d[mf][nf][3] + bias.y);
            *(float2*)(Crow + (size_t)r0 * TWO_D + c0)       = v0;
            *(float2*)(Crow + (size_t)(r0 + 8) * TWO_D + c0) = v1;
        }
    }
}

// ---------------------------------------------------------------------------
// Scores + class binning, 512 threads, per-thread 4q x 2s (B LDS halved vs
// R15: each bv feeds 4 q rows). ty = tid>>6 (warp-uniform, q rows ty*4..+3);
// tx = tid&63 (s cols tx, tx+64). Staging and epilogues identical to R15.
// Per-(q,s) j-accumulation order unchanged -> bit-identical part2.
// grid = (4 s-tiles, 4 q-stripes, 8 j-chunks), 512 threads.
// ---------------------------------------------------------------------------
#define V17S_DYN   33824   /* bytes: scr 33024 + lab 512 + seg 260 + pad */

__global__ void __launch_bounds__(512, 2)
v17_scores(const float* __restrict__ W2, const int* __restrict__ labels)
{
    extern __shared__ __align__(16) char dyn[];
    float2* Aq2 = (float2*)(dyn);                 // [2][8][34]
    float2* Bs2 = (float2*)(dyn + 4352);          // [2][8][130]
    float2* ws2 = (float2*)(dyn + 20992);         // [2][8]
    double* scr  = (double*)(dyn);                // [32][129] (phase 2 overlay)
    int*    lab2 = (int*)(dyn + 33024);           // [128]
    int*    seg  = (int*)(dyn + 33536);           // [65]

    const int tid    = threadIdx.x;
    const int sBase  = blockIdx.x * 128;
    const int qBase  = blockIdx.y * 32;
    const int jcBase = blockIdx.z * JPER;
    const int ty = tid >> 6;      // 0..7: q rows ty*4 .. ty*4+3 (warp-uniform)
    const int tx = tid & 63;      // s cols tx + l*64, l=0..1

    // A staging: threads 0..255, one f32x2 each (32 q x 8 jp)
    const int aq_q  = (tid >> 3) & 31;
    const int aq_jp = tid & 7;
    const size_t hqOff = (size_t)(qBase + aq_q) * TWO_D + jcBase + aq_jp * 2;
    // B staging: all 512, one float4-pair each (128 s x 4 j-groups of 4)
    const int bs_s  = tid >> 2;          // 0..127
    const int bs_g  = tid & 3;           // j group: jp = g*2, g*2+1
    const size_t hsOff = (size_t)(sBase + bs_s) * TWO_D + jcBase + bs_g * 4;

    float2 pa0, pa1, pw;
    float4 pb0, pb1;

    #define V17S_PRE(jt) do {                                              \
        if (tid < 256) {                                                   \
            pa0 = *(const float2*)(v17_hq0 + hqOff + (jt));                \
            pa1 = *(const float2*)(v17_hq1 + hqOff + (jt));                \
        }                                                                  \
        pb0 = *(const float4*)(v17_hs0 + hsOff + (jt));                    \
        pb1 = *(const float4*)(v17_hs1 + hsOff + (jt));                    \
        if (tid < 8) pw = *(const float2*)(W2 + jcBase + (jt) + tid * 2);  \
    } while (0)

    #define V17S_STAGE(buf) do {                                                            \
        if (tid < 256)                                                                       \
            Aq2[(buf)*272 + aq_jp*34 + aq_q] = make_float2(pa0.x + pa1.x, pa0.y + pa1.y);   \
        Bs2[(buf)*1040 + (bs_g*2+0)*130 + bs_s] = make_float2(pb0.x + pb1.x, pb0.y + pb1.y);\
        Bs2[(buf)*1040 + (bs_g*2+1)*130 + bs_s] = make_float2(pb0.z + pb1.z, pb0.w + pb1.w);\
        if (tid < 8) ws2[(buf)*8 + tid] = pw;                                               \
    } while (0)

    ull acc2[4][2] = {};     // [q 0..3][s-slot 0..1]

    V17S_PRE(0);
    V17S_STAGE(0);
    V17S_PRE(16);

    for (int it = 0; it < 12; it++) {
        const int buf = it & 1;
        __syncthreads();
        if (it < 11) {
            V17S_STAGE(buf ^ 1);
            if (it < 10) V17S_PRE((it + 2) * 16);
        }

        #pragma unroll
        for (int jp = 0; jp < 8; jp++) {
            const ull w2v = *(const ull*)&ws2[buf*8 + jp];
            // two LDS128 broadcasts: q rows ty*4..ty*4+3
            float4 ap0 = *(const float4*)&Aq2[buf*272 + jp*34 + ty*4];
            float4 ap1 = *(const float4*)&Aq2[buf*272 + jp*34 + ty*4 + 2];
            ull a[4];
            asm("mov.b64 %0, {%1,%2};" : "=l"(a[0])
                : "r"(__float_as_uint(ap0.x)), "r"(__float_as_uint(ap0.y)));
            asm("mov.b64 %0, {%1,%2};" : "=l"(a[1])
                : "r"(__float_as_uint(ap0.z)), "r"(__float_as_uint(ap0.w)));
            asm("mov.b64 %0, {%1,%2};" : "=l"(a[2])
                : "r"(__float_as_uint(ap1.x)), "r"(__float_as_uint(ap1.y)));
            asm("mov.b64 %0, {%1,%2};" : "=l"(a[3])
                : "r"(__float_as_uint(ap1.z)), "r"(__float_as_uint(ap1.w)));
            #pragma unroll
            for (int l = 0; l < 2; l++) {
                const ull bv = *(const ull*)&Bs2[buf*1040 + jp*130 + tx + l*64];
                #pragma unroll
                for (int i = 0; i < 4; i++) {
                    ull t0; V17_ADD2(t0, a[i], bv);
                    t0 = v17_relu2(t0);
                    V17_FMA2(acc2[i][l], t0, w2v);
                }
            }
        }
    }

    // ---- phase 2: overlay smem, write chunk scores, bin by class ----
    __syncthreads();

    #pragma unroll
    for (int i = 0; i < 4; i++)
        #pragma unroll
        for (int l = 0; l < 2; l++) {
            unsigned lo, hi;
            asm("mov.b64 {%0,%1}, %2;" : "=r"(lo), "=r"(hi) : "l"(acc2[i][l]));
            scr[(ty*4 + i) * 129 + tx + l*64] =
                (double)(__uint_as_float(lo) + __uint_as_float(hi));
        }
    if (tid < 128) lab2[tid] = labels[sBase + tid];
    __syncthreads();

    if (tid <= 64) {
        const int c = tid;
        int lo = 0, hi = 128;
        while (lo < hi) { int m = (lo + hi) >> 1; if (lab2[m] < c) lo = m + 1; else hi = m; }
        seg[tid] = lo;
    }
    __syncthreads();

    const int cb = blockIdx.z * 4 + blockIdx.x;
    double* outp = v17_part2 + ((size_t)cb * Q_N + qBase) * C_N;
    #pragma unroll
    for (int k = 0; k < 4; k++) {
        const int p  = tid + k * 512;
        const int qq = p >> 6;
        const int cc = p & 63;
        double ssum = 0.0;
        const int s0 = seg[cc], s1 = seg[cc + 1];
        for (int s = s0; s < s1; s++) ssum += scr[qq * 129 + s];
        outp[p] = ssum;
    }
}

// ---------------------------------------------------------------------------
// Light aggregate (VERBATIM R12): per-query block sums 32 class-binned
// partials in fixed order, counts via binary search, softmax/argmax/loss,
// ticket-merged final. grid = 128 blocks, 128 threads.
// ---------------------------------------------------------------------------
__global__ void v17_agg(const int* __restrict__ labels,
                        const int* __restrict__ targets,
                        const float* __restrict__ b2,
                        float* __restrict__ out, int out_size)
{
    __shared__ int    lab[S_N];
    __shared__ double aggv[C_N];
    __shared__ double redv[C_N];
    __shared__ int    redi[C_N];
    __shared__ double rede[C_N];
    __shared__ int    isLast;
    __shared__ double lred[Q_N];

    const int q   = blockIdx.x;
    const int tid = threadIdx.x;

    for (int i = tid; i < S_N; i += 128) lab[i] = labels[i];
    __syncthreads();

    if (tid < C_N) {
        const double* P = v17_part2 + (size_t)q * C_N + tid;
        double s0 = 0.0, s1 = 0.0, s2 = 0.0, s3 = 0.0;
        #pragma unroll
        for (int cb = 0; cb < NCB; cb += 4) {
            s0 += P[(size_t)(cb + 0) * (Q_N * C_N)];
            s1 += P[(size_t)(cb + 1) * (Q_N * C_N)];
            s2 += P[(size_t)(cb + 2) * (Q_N * C_N)];
            s3 += P[(size_t)(cb + 3) * (Q_N * C_N)];
        }
        const double tot = (s0 + s1) + (s2 + s3);

        const int c = tid;
        int lo = 0, hi = S_N;
        while (lo < hi) { int m = (lo + hi) >> 1; if (lab[m] < c) lo = m + 1; else hi = m; }
        int lo2 = lo, hi2 = S_N;
        while (lo2 < hi2) { int m = (lo2 + hi2) >> 1; if (lab[m] < c + 1) lo2 = m + 1; else hi2 = m; }
        const int cnt = lo2 - lo;

        aggv[tid] = tot / (double)(cnt > 1 ? cnt : 1) + (double)b2[0];
        redv[tid] = aggv[tid];
        redi[tid] = tid;
    }
    __syncthreads();

    #pragma unroll
    for (int off = C_N / 2; off > 0; off >>= 1) {
        if (tid < off) {
            if (redv[tid + off] > redv[tid] ||
                (redv[tid + off] == redv[tid] && redi[tid + off] < redi[tid])) {
                redv[tid] = redv[tid + off];
                redi[tid] = redi[tid + off];
            }
        }
        __syncthreads();
    }
    const double mx = redv[0];
    const int    am = redi[0];

    if (tid < C_N) rede[tid] = exp(aggv[tid] - mx);
    __syncthreads();
    #pragma unroll
    for (int off = C_N / 2; off > 0; off >>= 1) {
        if (tid < off) rede[tid] += rede[tid + off];
        __syncthreads();
    }

    if (tid == 0) {
        const int tgt = targets[q];
        const double logp = aggv[tgt] - mx - log(rede[0]);
        v17_loss[q] = -logp;
        if (1 + q < out_size) out[1 + q] = (am == tgt) ? 1.0f : 0.0f;
        __threadfence();
        unsigned tk = atomicAdd(&v17_ticket, 1u);
        isLast = (tk == (unsigned)(Q_N - 1));
    }
    __syncthreads();

    if (isLast) {
        __threadfence();
        lred[tid] = v17_loss[tid];
        __syncthreads();
        #pragma unroll
        for (int off = Q_N / 2; off > 0; off >>= 1) {
            if (tid < off) lred[tid] += lred[tid + off];
            __syncthreads();
        }
        if (tid == 0) {
            if (out_size > 0) out[0] = (float)(lred[0] / (double)Q_N);
            v17_ticket = 0;
        }
    }
}

// ---------------------------------------------------------------------------
extern "C" void kernel_launch(void* const* d_in, const int* in_sizes, int n_in,
                              void* d_out, int out_size)
{
    const float* query   = (const float*)d_in[0];
    const float* support = (const float*)d_in[1];
    const float* W1      = (const float*)d_in[2];
    const float* b1      = (const float*)d_in[3];
    const float* W2      = (const float*)d_in[4];
    const float* b2      = (const float*)d_in[5];
    const int*   labels  = (const int*)  d_in[6];
    const int*   targets = (const int*)  d_in[7];
    (void)in_sizes; (void)n_in;

    float* out = (float*)d_out;

    cudaFuncSetAttribute(v17_gemm, cudaFuncAttributeMaxDynamicSharedMemorySize, V17_SMEM);

    v17_gemm  <<<dim3(12, 10, 2), 256, V17_SMEM>>>(query, support, W1, b1);
    v17_scores<<<dim3(4, 4, JCHUNKS), 512, V17S_DYN>>>(W2, labels);
    v17_agg   <<<Q_N, 128>>>(labels, targets, b2, out, out_size);
}